// round 1
// baseline (speedup 1.0000x reference)
#include <cuda_runtime.h>
#include <math.h>

// Problem constants (fixed dataset shape)
constexpr int BSZ   = 2048;   // batch
constexpr int VIEWS = 2;      // views
constexpr int DIM   = 512;    // feature dim
constexpr int NTOT  = BSZ * VIEWS;  // 4096
constexpr float TEMP = 0.07f;
constexpr float RSQRT2PI = 0.3989422804014327f;

// ---------------- device scratch (static: no allocations allowed) -----------
__device__ float  g_F[(size_t)NTOT * DIM];        // gathered feats [N,D], 8MB
__device__ float2 g_tab[(size_t)BSZ * BSZ];       // (mask, delta) per (ib,jb), 32MB
__device__ float  g_S[BSZ];                       // positive-mask row sums
__device__ float  g_sorted[BSZ];                  // sorted labels
__device__ float  g_u[NTOT];                      // per-row uniformity accum
__device__ float  g_p[NTOT];                      // per-row alignment accum

// ---------------- K0: gather feats (view-major) + zero accumulators ---------
__global__ void k_prep(const float* __restrict__ feats) {
    int idx4 = blockIdx.x * blockDim.x + threadIdx.x;   // 0..524287 (float4 units)
    int i  = idx4 >> 7;          // row 0..4095   (128 float4 per row)
    int d4 = idx4 & 127;
    int b  = i & (BSZ - 1);
    int v  = i >> 11;
    const float4* src = reinterpret_cast<const float4*>(feats);
    float4 val = src[(size_t)(b * VIEWS + v) * 128 + d4];
    reinterpret_cast<float4*>(g_F)[(size_t)i * 128 + d4] = val;
    if (idx4 < NTOT) { g_u[idx4] = 0.f; g_p[idx4] = 0.f; }
}

// ---------------- K1: bitonic sort of 2048 labels (single block) ------------
__global__ void k_sort(const float* __restrict__ labels) {
    __shared__ float s[BSZ];
    int tid = threadIdx.x;                   // 1024 threads
    s[tid]        = labels[tid];
    s[tid + 1024] = labels[tid + 1024];
    __syncthreads();
    for (int k = 2; k <= BSZ; k <<= 1) {
        for (int j = k >> 1; j > 0; j >>= 1) {
            for (int i = tid; i < BSZ; i += 1024) {
                int ixj = i ^ j;
                if (ixj > i) {
                    bool up = ((i & k) == 0);
                    float a = s[i], bb = s[ixj];
                    if ((a > bb) == up) { s[i] = bb; s[ixj] = a; }
                }
            }
            __syncthreads();
        }
    }
    g_sorted[tid]        = s[tid];
    g_sorted[tid + 1024] = s[tid + 1024];
}

// ---------------- K2: build (mask, delta) table + S row sums ----------------
// tab[ib*B + jb] = ( g(l_ib, l_jb),  V * rank_of_ib_within_row_jb )
// rank = B - #{k : (l_jb - l_k)^2 <= (l_jb - l_ib)^2}   (two monotone-half
// binary searches over sorted labels; exact squared-compare semantics).
__global__ void k_tab(const float* __restrict__ labels) {
    __shared__ float s[BSZ];
    __shared__ float red[256];
    int tid = threadIdx.x;
    int ib  = blockIdx.x;
    for (int m = tid; m < BSZ; m += 256) s[m] = g_sorted[m];
    __syncthreads();
    float li = labels[ib];
    float rs = 0.f;
    for (int jb = tid; jb < BSZ; jb += 256) {
        float lj = labels[jb];
        float dl = li - lj;
        float t2 = dl * dl;
        float g  = expf(-0.5f * t2) * RSQRT2PI;
        float c  = lj;   // center = row label
        // iC: first index with s[m] >= c (c exists in the array)
        int lo = 0, hi = BSZ;
        while (lo < hi) { int mid = (lo + hi) >> 1; if (s[mid] < c) lo = mid + 1; else hi = mid; }
        int iC = lo;
        // left boundary: first m in [0,iC] with (c-s[m])^2 <= t2 (pred monotone F->T)
        lo = 0; hi = iC;
        while (lo < hi) { int mid = (lo + hi) >> 1; float d = c - s[mid];
                          if (d * d <= t2) hi = mid; else lo = mid + 1; }
        int iL = lo;
        // right boundary: last m in [iC,B-1] with (s[m]-c)^2 <= t2 (pred T->F)
        lo = iC; hi = BSZ - 1;
        while (lo < hi) { int mid = (lo + hi + 1) >> 1; float d = s[mid] - c;
                          if (d * d <= t2) lo = mid; else hi = mid - 1; }
        int iR = lo;
        int cnt = iR - iL + 1;
        float delta = (float)(VIEWS * (BSZ - cnt));
        g_tab[(size_t)ib * BSZ + jb] = make_float2(g, delta);
        rs += g;
    }
    red[tid] = rs; __syncthreads();
    for (int st = 128; st > 0; st >>= 1) { if (tid < st) red[tid] += red[tid + st]; __syncthreads(); }
    if (tid == 0) g_S[ib] = (float)VIEWS * red[0] - RSQRT2PI;
}

// ---------------- K3: fused symmetric SGEMM (F F^T / T) + epilogue ----------
// 128x128 tiles, lower triangle only; epilogue applied in both orientations
// for off-diagonal tiles. Per row i accumulate:
//   p_i = sum_{j!=i} mask_ij * (L_ij - Mc)
//   u_i = sum_{j!=i} exp(L_ij - Mc) * delta_ij
__global__ __launch_bounds__(256, 2) void k_main() {
    __shared__ float As[2][128][17];
    __shared__ float Bs[2][128][17];
    __shared__ float uRow[128], pRow[128], uCol[128], pCol[128];

    int tid = threadIdx.x;
    int t   = blockIdx.x;
    int bi  = (int)((sqrtf(8.f * (float)t + 1.f) - 1.f) * 0.5f);
    while ((bi + 1) * (bi + 2) / 2 <= t) bi++;
    while (bi * (bi + 1) / 2 > t) bi--;
    int bj = t - bi * (bi + 1) / 2;
    int i0 = bi * 128, j0 = bj * 128;
    bool diag = (bi == bj);

    if (tid < 128) { uRow[tid] = 0.f; pRow[tid] = 0.f; uCol[tid] = 0.f; pCol[tid] = 0.f; }

    int tx = tid & 15, ty = tid >> 4;
    float acc[8][8];
    #pragma unroll
    for (int m = 0; m < 8; m++)
        #pragma unroll
        for (int n = 0; n < 8; n++) acc[m][n] = 0.f;

    // global-load assignment: 512 float4 per operand tile, 2 per thread
    int r0 = tid >> 2,          c40 = tid & 3;
    int r1 = (tid + 256) >> 2,  c41 = (tid + 256) & 3;
    const float4* F4 = reinterpret_cast<const float4*>(g_F);

    // preload tile 0
    {
        float4 a0 = F4[(size_t)(i0 + r0) * 128 + c40];
        float4 a1 = F4[(size_t)(i0 + r1) * 128 + c41];
        float4 b0 = F4[(size_t)(j0 + r0) * 128 + c40];
        float4 b1 = F4[(size_t)(j0 + r1) * 128 + c41];
        As[0][r0][c40*4+0]=a0.x; As[0][r0][c40*4+1]=a0.y; As[0][r0][c40*4+2]=a0.z; As[0][r0][c40*4+3]=a0.w;
        As[0][r1][c41*4+0]=a1.x; As[0][r1][c41*4+1]=a1.y; As[0][r1][c41*4+2]=a1.z; As[0][r1][c41*4+3]=a1.w;
        Bs[0][r0][c40*4+0]=b0.x; Bs[0][r0][c40*4+1]=b0.y; Bs[0][r0][c40*4+2]=b0.z; Bs[0][r0][c40*4+3]=b0.w;
        Bs[0][r1][c41*4+0]=b1.x; Bs[0][r1][c41*4+1]=b1.y; Bs[0][r1][c41*4+2]=b1.z; Bs[0][r1][c41*4+3]=b1.w;
    }
    __syncthreads();

    for (int kt = 0; kt < 32; kt++) {
        int cur = kt & 1;
        float4 a0, a1, b0, b1;
        if (kt < 31) {
            int kb = (kt + 1) * 4;
            a0 = F4[(size_t)(i0 + r0) * 128 + kb + c40];
            a1 = F4[(size_t)(i0 + r1) * 128 + kb + c41];
            b0 = F4[(size_t)(j0 + r0) * 128 + kb + c40];
            b1 = F4[(size_t)(j0 + r1) * 128 + kb + c41];
        }
        #pragma unroll
        for (int k = 0; k < 16; k++) {
            float av[8], bv[8];
            #pragma unroll
            for (int q = 0; q < 4; q++) {
                av[q]     = As[cur][ty*4 + q][k];
                av[4 + q] = As[cur][64 + ty*4 + q][k];
                bv[q]     = Bs[cur][tx*4 + q][k];
                bv[4 + q] = Bs[cur][64 + tx*4 + q][k];
            }
            #pragma unroll
            for (int m = 0; m < 8; m++)
                #pragma unroll
                for (int n = 0; n < 8; n++)
                    acc[m][n] = fmaf(av[m], bv[n], acc[m][n]);
        }
        if (kt < 31) {
            int nxt = cur ^ 1;
            As[nxt][r0][c40*4+0]=a0.x; As[nxt][r0][c40*4+1]=a0.y; As[nxt][r0][c40*4+2]=a0.z; As[nxt][r0][c40*4+3]=a0.w;
            As[nxt][r1][c41*4+0]=a1.x; As[nxt][r1][c41*4+1]=a1.y; As[nxt][r1][c41*4+2]=a1.z; As[nxt][r1][c41*4+3]=a1.w;
            Bs[nxt][r0][c40*4+0]=b0.x; Bs[nxt][r0][c40*4+1]=b0.y; Bs[nxt][r0][c40*4+2]=b0.z; Bs[nxt][r0][c40*4+3]=b0.w;
            Bs[nxt][r1][c41*4+0]=b1.x; Bs[nxt][r1][c41*4+1]=b1.y; Bs[nxt][r1][c41*4+2]=b1.z; Bs[nxt][r1][c41*4+3]=b1.w;
        }
        __syncthreads();
    }

    // ---- epilogue ----
    const float invT = 1.0f / TEMP;
    const float Mc   = invT;               // any constant shift is exact here
    int iB = i0 & (BSZ - 1);
    int jB = j0 & (BSZ - 1);
    float uR[8] = {0}, pR[8] = {0}, uC[8] = {0}, pC[8] = {0};
    #pragma unroll
    for (int m = 0; m < 8; m++) {
        int r = (m < 4) ? (ty*4 + m) : (64 + ty*4 + m - 4);
        #pragma unroll
        for (int n = 0; n < 8; n++) {
            int c = (n < 4) ? (tx*4 + n) : (64 + tx*4 + n - 4);
            float L = acc[m][n] * invT;
            float x = L - Mc;
            float2 md = g_tab[(size_t)(iB + r) * BSZ + (jB + c)];
            float e = expf(x);
            bool skip = diag && (r == c);    // global i == j
            if (!skip) {
                uR[m] += e * md.y;
                pR[m]  = fmaf(md.x, x, pR[m]);
                if (!diag) {
                    float d2 = g_tab[(size_t)(jB + c) * BSZ + (iB + r)].y;  // transposed delta
                    uC[n] += e * d2;
                    pC[n]  = fmaf(md.x, x, pC[n]);   // mask is symmetric
                }
            }
        }
    }
    #pragma unroll
    for (int m = 0; m < 8; m++) {
        int r = (m < 4) ? (ty*4 + m) : (64 + ty*4 + m - 4);
        atomicAdd(&uRow[r], uR[m]);
        atomicAdd(&pRow[r], pR[m]);
    }
    if (!diag) {
        #pragma unroll
        for (int n = 0; n < 8; n++) {
            int c = (n < 4) ? (tx*4 + n) : (64 + tx*4 + n - 4);
            atomicAdd(&uCol[c], uC[n]);
            atomicAdd(&pCol[c], pC[n]);
        }
    }
    __syncthreads();
    if (tid < 128) {
        atomicAdd(&g_u[i0 + tid], uRow[tid]);
        atomicAdd(&g_p[i0 + tid], pRow[tid]);
        if (!diag) {
            atomicAdd(&g_u[j0 + tid], uCol[tid]);
            atomicAdd(&g_p[j0 + tid], pCol[tid]);
        }
    }
}

// ---------------- K4: final reduction to scalar loss ------------------------
__global__ void k_final(float* __restrict__ out) {
    __shared__ float red[512];
    int tid = threadIdx.x;
    float sum = 0.f;
    for (int i = tid; i < NTOT; i += 512) {
        float lp = g_p[i] / g_S[i & (BSZ - 1)] - logf(g_u[i]);
        sum += lp;
    }
    red[tid] = sum; __syncthreads();
    for (int st = 256; st > 0; st >>= 1) { if (tid < st) red[tid] += red[tid + st]; __syncthreads(); }
    if (tid == 0) out[0] = -red[0] / (float)NTOT;   // TEMP/BASE_TEMPERATURE == 1
}

// ---------------- entry -----------------------------------------------------
extern "C" void kernel_launch(void* const* d_in, const int* in_sizes, int n_in,
                              void* d_out, int out_size) {
    (void)in_sizes; (void)n_in; (void)out_size;
    const float* feats  = (const float*)d_in[0];   // [2048, 2, 512] f32
    const float* labels = (const float*)d_in[1];   // [2048] f32
    float* out = (float*)d_out;

    k_prep <<<2048, 256>>>(feats);
    k_sort <<<1, 1024>>>(labels);
    k_tab  <<<2048, 256>>>(labels);
    k_main <<<528, 256>>>();
    k_final<<<1, 512>>>(out);
}

// round 3
// speedup vs baseline: 1.7285x; 1.7285x over previous
#include <cuda_runtime.h>
#include <cuda_bf16.h>
#include <cstdint>
#include <math.h>

// ---------------- problem constants ----------------
constexpr int BSZ   = 2048;
constexpr int VIEWS = 2;
constexpr int DIM   = 512;
constexpr int NTOT  = BSZ * VIEWS;          // 4096
constexpr float TEMP = 0.07f;
constexpr float RSQRT2PI = 0.3989422804014327f;

// GEMM tiling: 128x128 CTA tile, 8 warps of 64x32, K-chunks of 64
constexpr int KC = 64;
constexpr int NCHUNK = DIM / KC;             // 8
constexpr int LDSTR = 72;                    // smem row stride in bf16 (144B, conflict-free ldmatrix)
constexpr int OPB = 128 * LDSTR * 2;         // 18432 B per operand tile
constexpr int STG = 4 * OPB;                 // Ahi|Alo|Bhi|Blo = 73728 B per stage
constexpr int DSMEM = 2 * STG;               // 147456 B

// ---------------- device scratch --------------------
__device__ __nv_bfloat16 g_Fhi[(size_t)NTOT * DIM];     // 4 MB
__device__ __nv_bfloat16 g_Flo[(size_t)NTOT * DIM];     // 4 MB
__device__ unsigned short g_dt [(size_t)BSZ * BSZ];     // delta, 8 MB
__device__ unsigned short g_dtT[(size_t)BSZ * BSZ];     // delta^T, 8 MB
__device__ float g_S[BSZ];
__device__ float g_sorted[BSZ];
__device__ float g_u[NTOT];
__device__ float g_p[NTOT];

// ---------------- PTX helpers -----------------------
__device__ __forceinline__ uint32_t smem_u32(const void* p) {
    uint32_t a;
    asm("{ .reg .u64 t; cvta.to.shared.u64 t, %1; cvt.u32.u64 %0, t; }" : "=r"(a) : "l"(p));
    return a;
}
__device__ __forceinline__ void cpa16(uint32_t d, const void* s) {
    asm volatile("cp.async.cg.shared.global [%0], [%1], 16;" :: "r"(d), "l"(s) : "memory");
}
#define CP_COMMIT() asm volatile("cp.async.commit_group;" ::: "memory")
#define CP_WAIT0()  asm volatile("cp.async.wait_group 0;" ::: "memory")
#define CP_WAIT1()  asm volatile("cp.async.wait_group 1;" ::: "memory")
__device__ __forceinline__ void ldsm4(uint32_t* r, uint32_t a) {
    asm volatile("ldmatrix.sync.aligned.m8n8.x4.shared.b16 {%0,%1,%2,%3}, [%4];"
        : "=r"(r[0]), "=r"(r[1]), "=r"(r[2]), "=r"(r[3]) : "r"(a));
}
__device__ __forceinline__ void mma_bf16(float* c,
    uint32_t a0, uint32_t a1, uint32_t a2, uint32_t a3, uint32_t b0, uint32_t b1) {
    asm volatile("mma.sync.aligned.m16n8k16.row.col.f32.bf16.bf16.f32 "
        "{%0,%1,%2,%3}, {%4,%5,%6,%7}, {%8,%9}, {%0,%1,%2,%3};"
        : "+f"(c[0]), "+f"(c[1]), "+f"(c[2]), "+f"(c[3])
        : "r"(a0), "r"(a1), "r"(a2), "r"(a3), "r"(b0), "r"(b1));
}

// ---------------- K0: bf16 hi/lo split + zero accums -------------------------
__global__ void k_prep(const float* __restrict__ feats) {
    int idx = blockIdx.x * blockDim.x + threadIdx.x;   // 262144 = 4096 rows * 64 groups
    int row = idx >> 6;
    int c0  = (idx & 63) * 8;
    int b = row & (BSZ - 1), v = row >> 11;
    const float* src = feats + ((size_t)(b * VIEWS + v) * DIM + c0);
    float4 f0 = *(const float4*)src;
    float4 f1 = *(const float4*)(src + 4);
    float vals[8] = {f0.x, f0.y, f0.z, f0.w, f1.x, f1.y, f1.z, f1.w};
    __nv_bfloat16 hi[8], lo[8];
#pragma unroll
    for (int e = 0; e < 8; e++) {
        hi[e] = __float2bfloat16(vals[e]);
        lo[e] = __float2bfloat16(vals[e] - __bfloat162float(hi[e]));
    }
    size_t dst = (size_t)row * DIM + c0;
    *(uint4*)&g_Fhi[dst] = *(const uint4*)hi;
    *(uint4*)&g_Flo[dst] = *(const uint4*)lo;
    if (idx < NTOT) { g_u[idx] = 0.f; g_p[idx] = 0.f; }
}

// ---------------- K1: bitonic sort of labels ---------------------------------
__global__ void k_sort(const float* __restrict__ labels) {
    __shared__ float s[BSZ];
    int tid = threadIdx.x;
    s[tid] = labels[tid]; s[tid + 1024] = labels[tid + 1024];
    __syncthreads();
    for (int k = 2; k <= BSZ; k <<= 1)
        for (int j = k >> 1; j > 0; j >>= 1) {
            for (int i = tid; i < BSZ; i += 1024) {
                int ixj = i ^ j;
                if (ixj > i) {
                    bool up = ((i & k) == 0);
                    float a = s[i], bb = s[ixj];
                    if ((a > bb) == up) { s[i] = bb; s[ixj] = a; }
                }
            }
            __syncthreads();
        }
    g_sorted[tid] = s[tid]; g_sorted[tid + 1024] = s[tid + 1024];
}

// ---------------- K2: delta table (uint16) + S row sums ----------------------
__global__ void k_tab(const float* __restrict__ labels) {
    __shared__ float s[BSZ];
    __shared__ float red[256];
    int tid = threadIdx.x;
    int ib  = blockIdx.x;
    for (int m = tid; m < BSZ; m += 256) s[m] = g_sorted[m];
    __syncthreads();
    float li = labels[ib];
    float rs = 0.f;
    for (int jb = tid; jb < BSZ; jb += 256) {
        float lj = labels[jb];
        float dl = li - lj;
        float t2 = dl * dl;
        rs += expf(-0.5f * t2) * RSQRT2PI;
        float c = lj;
        int lo = 0, hi = BSZ;
        while (lo < hi) { int mid = (lo + hi) >> 1; if (s[mid] < c) lo = mid + 1; else hi = mid; }
        int iC = lo;
        lo = 0; hi = iC;
        while (lo < hi) { int mid = (lo + hi) >> 1; float d = c - s[mid];
                          if (d * d <= t2) hi = mid; else lo = mid + 1; }
        int iL = lo;
        lo = iC; hi = BSZ - 1;
        while (lo < hi) { int mid = (lo + hi + 1) >> 1; float d = s[mid] - c;
                          if (d * d <= t2) lo = mid; else hi = mid - 1; }
        int iR = lo;
        int cnt = iR - iL + 1;
        g_dt[(size_t)ib * BSZ + jb] = (unsigned short)(VIEWS * (BSZ - cnt));
    }
    red[tid] = rs; __syncthreads();
    for (int st = 128; st > 0; st >>= 1) { if (tid < st) red[tid] += red[tid + st]; __syncthreads(); }
    if (tid == 0) g_S[ib] = (float)VIEWS * red[0] - RSQRT2PI;
}

// ---------------- K2b: transpose delta table ---------------------------------
__global__ void k_transp() {
    __shared__ unsigned short tile[64][72];
    int bx = blockIdx.x & 31, by = blockIdx.x >> 5;
    int r  = threadIdx.x >> 2;
    int c0 = (threadIdx.x & 3) * 16;
    const unsigned short* src = g_dt + (size_t)(by * 64 + r) * BSZ + bx * 64 + c0;
    *(uint4*)&tile[r][c0]     = *(const uint4*)src;
    *(uint4*)&tile[r][c0 + 8] = *(const uint4*)(src + 8);
    __syncthreads();
    unsigned short ov[16];
#pragma unroll
    for (int k = 0; k < 16; k++) ov[k] = tile[c0 + k][r];
    unsigned short* dst = g_dtT + (size_t)(bx * 64 + r) * BSZ + by * 64 + c0;
    *(uint4*)dst       = *(const uint4*)ov;
    *(uint4*)(dst + 8) = *(const uint4*)(ov + 8);
}

// ---------------- K3: mma.sync bf16x3 GEMM + fused epilogue ------------------
__global__ __launch_bounds__(256, 1) void k_main(const float* __restrict__ labels) {
    extern __shared__ __align__(16) char smem[];
    __shared__ float uRow[128], pRow[128], uCol[128], pCol[128];
    __shared__ float slabA[128], slabB[128];
    uint32_t sb = smem_u32(smem);
    int tid = threadIdx.x, wid = tid >> 5, lane = tid & 31;

    // triangular tile index
    int t  = blockIdx.x;
    int bi = (int)((sqrtf(8.f * (float)t + 1.f) - 1.f) * 0.5f);
    while ((bi + 1) * (bi + 2) / 2 <= t) bi++;
    while (bi * (bi + 1) / 2 > t) bi--;
    int bj = t - bi * (bi + 1) / 2;
    int i0 = bi * 128, j0 = bj * 128;
    bool diag = (bi == bj);

    if (tid < 128) {
        uRow[tid] = 0.f; pRow[tid] = 0.f; uCol[tid] = 0.f; pCol[tid] = 0.f;
        slabA[tid] = labels[(i0 + tid) & (BSZ - 1)];
        slabB[tid] = labels[(j0 + tid) & (BSZ - 1)];
    }

    int lr = tid >> 3, lch = tid & 7;      // cp.async assignment
    auto issue = [&](int c) {
        uint32_t stg = sb + (uint32_t)(c & 1) * STG;
        int gco = c * KC + lch * 8;
#pragma unroll
        for (int rr = 0; rr < 4; rr++) {
            int row = rr * 32 + lr;
            uint32_t d = stg + (uint32_t)(row * (LDSTR * 2) + lch * 16);
            cpa16(d,           &g_Fhi[(size_t)(i0 + row) * DIM + gco]);
            cpa16(d + OPB,     &g_Flo[(size_t)(i0 + row) * DIM + gco]);
            cpa16(d + 2 * OPB, &g_Fhi[(size_t)(j0 + row) * DIM + gco]);
            cpa16(d + 3 * OPB, &g_Flo[(size_t)(j0 + row) * DIM + gco]);
        }
        CP_COMMIT();
    };

    int wr = wid & 1, wc = wid >> 1;       // warp = 64 rows x 32 cols
    int arow = (lane & 7) + ((lane >> 3) & 1) * 8;
    int acol = ((lane >> 4) & 1) * 8;
    int brow = (lane & 7) + ((lane >> 4) & 1) * 8;
    int bcol = ((lane >> 3) & 1) * 8;

    float acc[4][4][4];
#pragma unroll
    for (int mt = 0; mt < 4; mt++)
#pragma unroll
        for (int nt = 0; nt < 4; nt++)
#pragma unroll
            for (int e = 0; e < 4; e++) acc[mt][nt][e] = 0.f;

    issue(0); issue(1);
    for (int c = 0; c < NCHUNK; c++) {
        if (c == NCHUNK - 1) { CP_WAIT0(); } else { CP_WAIT1(); }
        __syncthreads();
        uint32_t stg = sb + (uint32_t)(c & 1) * STG;
#pragma unroll
        for (int ks = 0; ks < 4; ks++) {
            int k0 = ks * 16;
            uint32_t ah[4][4], al[4][4], bh[2][4], bl[2][4];
#pragma unroll
            for (int mt = 0; mt < 4; mt++) {
                int row = wr * 64 + mt * 16 + arow;
                uint32_t ad = stg + (uint32_t)(row * 144 + (k0 + acol) * 2);
                ldsm4(ah[mt], ad);
                ldsm4(al[mt], ad + OPB);
            }
#pragma unroll
            for (int pr = 0; pr < 2; pr++) {
                int row = wc * 32 + pr * 16 + brow;
                uint32_t bd = stg + (uint32_t)(2 * OPB + row * 144 + (k0 + bcol) * 2);
                ldsm4(bh[pr], bd);
                ldsm4(bl[pr], bd + OPB);
            }
#pragma unroll
            for (int sp = 0; sp < 3; sp++) {
#pragma unroll
                for (int mt = 0; mt < 4; mt++) {
#pragma unroll
                    for (int nt = 0; nt < 4; nt++) {
                        int pr = nt >> 1, h2 = (nt & 1) * 2;
                        uint32_t a0, a1, a2, a3, b0, b1;
                        if (sp == 2) { a0 = al[mt][0]; a1 = al[mt][1]; a2 = al[mt][2]; a3 = al[mt][3]; }
                        else         { a0 = ah[mt][0]; a1 = ah[mt][1]; a2 = ah[mt][2]; a3 = ah[mt][3]; }
                        if (sp == 1) { b0 = bl[pr][h2]; b1 = bl[pr][h2 + 1]; }
                        else         { b0 = bh[pr][h2]; b1 = bh[pr][h2 + 1]; }
                        mma_bf16(acc[mt][nt], a0, a1, a2, a3, b0, b1);
                    }
                }
            }
        }
        __syncthreads();
        if (c + 2 < NCHUNK) issue(c + 2);
    }

    // ---- fused epilogue ----
    const float invT = 1.0f / TEMP;
    float uR[8], pR[8], uC[8], pC[8];
#pragma unroll
    for (int e = 0; e < 8; e++) { uR[e] = 0.f; pR[e] = 0.f; uC[e] = 0.f; pC[e] = 0.f; }
    int rq = lane >> 2, cq = 2 * (lane & 3);
#pragma unroll
    for (int mt = 0; mt < 4; mt++) {
#pragma unroll
        for (int h = 0; h < 2; h++) {
            int r  = wr * 64 + mt * 16 + rq + h * 8;
            int iB = (i0 + r) & (BSZ - 1);
            float li = slabA[r];
            const unsigned short* dtrow = g_dt  + (size_t)iB * BSZ;
            const unsigned short* dTrow = g_dtT + (size_t)iB * BSZ;
            int ridx = mt * 2 + h;
#pragma unroll
            for (int nt = 0; nt < 4; nt++) {
                int c2  = wc * 32 + nt * 8 + cq;
                int jB2 = (j0 + c2) & (BSZ - 1);
                uint32_t dp  = *(const uint32_t*)(dtrow + jB2);
                uint32_t dTp = *(const uint32_t*)(dTrow + jB2);
#pragma unroll
                for (int e = 0; e < 2; e++) {
                    int cc = c2 + e;
                    float a = acc[mt][nt][h * 2 + e];
                    float x = (a - 1.0f) * invT;
                    float lj = slabB[cc];
                    float dd = li - lj;
                    float m  = __expf(-0.5f * dd * dd) * RSQRT2PI;
                    float ex = __expf(x);
                    float dv  = (float)((e ? (dp >> 16)  : dp)  & 0xFFFF);
                    float dTv = (float)((e ? (dTp >> 16) : dTp) & 0xFFFF);
                    bool skip = diag && (r == cc);
                    if (!skip) {
                        uR[ridx] += ex * dv;
                        pR[ridx]  = fmaf(m, x, pR[ridx]);
                        if (!diag) {
                            int cidx = nt * 2 + e;
                            uC[cidx] += ex * dTv;
                            pC[cidx]  = fmaf(m, x, pC[cidx]);
                        }
                    }
                }
            }
        }
    }
#pragma unroll
    for (int mt = 0; mt < 4; mt++)
#pragma unroll
        for (int h = 0; h < 2; h++) {
            int r = wr * 64 + mt * 16 + rq + h * 8;
            atomicAdd(&uRow[r], uR[mt * 2 + h]);
            atomicAdd(&pRow[r], pR[mt * 2 + h]);
        }
    if (!diag) {
#pragma unroll
        for (int nt = 0; nt < 4; nt++)
#pragma unroll
            for (int e = 0; e < 2; e++) {
                int cc = wc * 32 + nt * 8 + cq + e;
                atomicAdd(&uCol[cc], uC[nt * 2 + e]);
                atomicAdd(&pCol[cc], pC[nt * 2 + e]);
            }
    }
    __syncthreads();
    if (tid < 128) {
        atomicAdd(&g_u[i0 + tid], uRow[tid]);
        atomicAdd(&g_p[i0 + tid], pRow[tid]);
        if (!diag) {
            atomicAdd(&g_u[j0 + tid], uCol[tid]);
            atomicAdd(&g_p[j0 + tid], pCol[tid]);
        }
    }
}

// ---------------- K4: final reduction -----------------------------------------
__global__ void k_final(float* __restrict__ out) {
    __shared__ float red[512];
    int tid = threadIdx.x;
    float sum = 0.f;
    for (int i = tid; i < NTOT; i += 512) {
        float lp = g_p[i] / g_S[i & (BSZ - 1)] - logf(g_u[i]);
        sum += lp;
    }
    red[tid] = sum; __syncthreads();
    for (int st = 256; st > 0; st >>= 1) { if (tid < st) red[tid] += red[tid + st]; __syncthreads(); }
    if (tid == 0) out[0] = -red[0] / (float)NTOT;
}

// ---------------- entry --------------------------------------------------------
extern "C" void kernel_launch(void* const* d_in, const int* in_sizes, int n_in,
                              void* d_out, int out_size) {
    (void)in_sizes; (void)n_in; (void)out_size;
    const float* feats  = (const float*)d_in[0];
    const float* labels = (const float*)d_in[1];
    float* out = (float*)d_out;

    cudaFuncSetAttribute(k_main, cudaFuncAttributeMaxDynamicSharedMemorySize, DSMEM);

    k_prep  <<<1024, 256>>>(feats);
    k_sort  <<<1, 1024>>>(labels);
    k_tab   <<<2048, 256>>>(labels);
    k_transp<<<1024, 256>>>();
    k_main  <<<528, 256, DSMEM>>>(labels);
    k_final <<<1, 512>>>(out);
}

// round 4
// speedup vs baseline: 2.2611x; 1.3081x over previous
#include <cuda_runtime.h>
#include <cuda_bf16.h>
#include <cstdint>
#include <math.h>

// ---------------- problem constants ----------------
constexpr int BSZ   = 2048;
constexpr int VIEWS = 2;
constexpr int DIM   = 512;
constexpr int NTOT  = BSZ * VIEWS;          // 4096
constexpr float TEMP = 0.07f;
constexpr float RSQRT2PI = 0.3989422804014327f;

// GEMM tiling: 128x128 CTA tile, 8 warps of 64x32, K-chunks of 32
constexpr int KC = 32;
constexpr int NCHUNK = DIM / KC;             // 16
constexpr int LDB = 80;                      // smem row stride bytes (64B data + 16B pad)
constexpr int OPB = 128 * LDB;               // 10240 B per operand tile
constexpr int STG = 4 * OPB;                 // Ahi|Alo|Bhi|Blo = 40960 B per stage
constexpr int DSMEM = 2 * STG;               // 81920 B  -> 2 CTAs/SM

// ---------------- device scratch --------------------
__device__ __nv_bfloat16 g_Fhi[(size_t)NTOT * DIM];     // 4 MB
__device__ __nv_bfloat16 g_Flo[(size_t)NTOT * DIM];     // 4 MB
__device__ unsigned short g_dt [(size_t)BSZ * BSZ];     // delta[i][j], 8 MB
__device__ unsigned short g_dtT[(size_t)BSZ * BSZ];     // delta[j][i] (built first), 8 MB
__device__ float g_S[BSZ];
__device__ float g_sorted[BSZ];
__device__ float g_u[NTOT];
__device__ float g_p[NTOT];

// ---------------- PTX helpers -----------------------
__device__ __forceinline__ uint32_t smem_u32(const void* p) {
    uint32_t a;
    asm("{ .reg .u64 t; cvta.to.shared.u64 t, %1; cvt.u32.u64 %0, t; }" : "=r"(a) : "l"(p));
    return a;
}
__device__ __forceinline__ void cpa16(uint32_t d, const void* s) {
    asm volatile("cp.async.cg.shared.global [%0], [%1], 16;" :: "r"(d), "l"(s) : "memory");
}
#define CP_COMMIT() asm volatile("cp.async.commit_group;" ::: "memory")
#define CP_WAIT0()  asm volatile("cp.async.wait_group 0;" ::: "memory")
#define CP_WAIT1()  asm volatile("cp.async.wait_group 1;" ::: "memory")
__device__ __forceinline__ void ldsm4(uint32_t* r, uint32_t a) {
    asm volatile("ldmatrix.sync.aligned.m8n8.x4.shared.b16 {%0,%1,%2,%3}, [%4];"
        : "=r"(r[0]), "=r"(r[1]), "=r"(r[2]), "=r"(r[3]) : "r"(a));
}
__device__ __forceinline__ void mma_bf16(float* c,
    uint32_t a0, uint32_t a1, uint32_t a2, uint32_t a3, uint32_t b0, uint32_t b1) {
    asm volatile("mma.sync.aligned.m16n8k16.row.col.f32.bf16.bf16.f32 "
        "{%0,%1,%2,%3}, {%4,%5,%6,%7}, {%8,%9}, {%0,%1,%2,%3};"
        : "+f"(c[0]), "+f"(c[1]), "+f"(c[2]), "+f"(c[3])
        : "r"(a0), "r"(a1), "r"(a2), "r"(a3), "r"(b0), "r"(b1));
}

// ---------------- K0: bf16 hi/lo split + zero accums -------------------------
__global__ void k_prep(const float* __restrict__ feats) {
    int idx = blockIdx.x * blockDim.x + threadIdx.x;   // 262144 = 4096 rows * 64 groups
    int row = idx >> 6;
    int c0  = (idx & 63) * 8;
    int b = row & (BSZ - 1), v = row >> 11;
    const float* src = feats + ((size_t)(b * VIEWS + v) * DIM + c0);
    float4 f0 = *(const float4*)src;
    float4 f1 = *(const float4*)(src + 4);
    float vals[8] = {f0.x, f0.y, f0.z, f0.w, f1.x, f1.y, f1.z, f1.w};
    __nv_bfloat16 hi[8], lo[8];
#pragma unroll
    for (int e = 0; e < 8; e++) {
        hi[e] = __float2bfloat16(vals[e]);
        lo[e] = __float2bfloat16(vals[e] - __bfloat162float(hi[e]));
    }
    size_t dst = (size_t)row * DIM + c0;
    *(uint4*)&g_Fhi[dst] = *(const uint4*)hi;
    *(uint4*)&g_Flo[dst] = *(const uint4*)lo;
    if (idx < NTOT) { g_u[idx] = 0.f; g_p[idx] = 0.f; }
}

// ---------------- K1: bitonic sort of labels ---------------------------------
__global__ void k_sort(const float* __restrict__ labels) {
    __shared__ float s[BSZ];
    int tid = threadIdx.x;
    s[tid] = labels[tid]; s[tid + 1024] = labels[tid + 1024];
    __syncthreads();
    for (int k = 2; k <= BSZ; k <<= 1)
        for (int j = k >> 1; j > 0; j >>= 1) {
            for (int i = tid; i < BSZ; i += 1024) {
                int ixj = i ^ j;
                if (ixj > i) {
                    bool up = ((i & k) == 0);
                    float a = s[i], bb = s[ixj];
                    if ((a > bb) == up) { s[i] = bb; s[ixj] = a; }
                }
            }
            __syncthreads();
        }
    g_sorted[tid] = s[tid]; g_sorted[tid + 1024] = s[tid + 1024];
}

// ---------------- K2: delta^T table (uint16) + S row sums --------------------
// block = row CENTER jb; per target ib:  cnt = #{k : (c-l_k)^2 <= (c-l_ib)^2}
// center search hoisted out of the target loop; the two window searches are
// independent -> ILP. Writes g_dtT[jb][ib] = delta[ib][jb] contiguously.
__global__ void k_tab(const float* __restrict__ labels) {
    __shared__ float s[BSZ];
    __shared__ float red[256];
    int tid = threadIdx.x;
    int jb  = blockIdx.x;
    for (int m = tid; m < BSZ; m += 256) s[m] = g_sorted[m];
    __syncthreads();
    float c = labels[jb];
    // iC: first index with s[m] >= c (hoisted; c exists in the array)
    int lo = 0, hi = BSZ;
    while (lo < hi) { int mid = (lo + hi) >> 1; if (s[mid] < c) lo = mid + 1; else hi = mid; }
    int iC = lo;
    float rs = 0.f;
    for (int ib = tid; ib < BSZ; ib += 256) {
        float li = labels[ib];
        float dl = c - li;
        float t2 = dl * dl;
        rs += expf(-0.5f * t2) * RSQRT2PI;
        // left boundary: first m in [0,iC] with (c-s[m])^2 <= t2
        int l0 = 0, l1 = iC;
        // right boundary: last m in [iC,B-1] with (s[m]-c)^2 <= t2
        int r0 = iC, r1 = BSZ - 1;
#pragma unroll 1
        while (l0 < l1 || r0 < r1) {
            if (l0 < l1) { int mid = (l0 + l1) >> 1; float d = c - s[mid];
                           if (d * d <= t2) l1 = mid; else l0 = mid + 1; }
            if (r0 < r1) { int mid = (r0 + r1 + 1) >> 1; float d = s[mid] - c;
                           if (d * d <= t2) r0 = mid; else r1 = mid - 1; }
        }
        int cnt = r0 - l0 + 1;
        g_dtT[(size_t)jb * BSZ + ib] = (unsigned short)(VIEWS * (BSZ - cnt));
    }
    red[tid] = rs; __syncthreads();
    for (int st = 128; st > 0; st >>= 1) { if (tid < st) red[tid] += red[tid + st]; __syncthreads(); }
    if (tid == 0) g_S[jb] = (float)VIEWS * red[0] - RSQRT2PI;
}

// ---------------- K2b: transpose delta^T -> delta -----------------------------
__global__ void k_transp() {
    __shared__ unsigned short tile[64][72];
    int bx = blockIdx.x & 31, by = blockIdx.x >> 5;
    int r  = threadIdx.x >> 2;
    int c0 = (threadIdx.x & 3) * 16;
    const unsigned short* src = g_dtT + (size_t)(by * 64 + r) * BSZ + bx * 64 + c0;
    *(uint4*)&tile[r][c0]     = *(const uint4*)src;
    *(uint4*)&tile[r][c0 + 8] = *(const uint4*)(src + 8);
    __syncthreads();
    unsigned short ov[16];
#pragma unroll
    for (int k = 0; k < 16; k++) ov[k] = tile[c0 + k][r];
    unsigned short* dst = g_dt + (size_t)(bx * 64 + r) * BSZ + by * 64 + c0;
    *(uint4*)dst       = *(const uint4*)ov;
    *(uint4*)(dst + 8) = *(const uint4*)(ov + 8);
}

// ---------------- K3: mma.sync bf16x3 GEMM + fused epilogue ------------------
__global__ __launch_bounds__(256, 2) void k_main(const float* __restrict__ labels) {
    extern __shared__ __align__(16) char smem[];
    __shared__ float uRow[128], pRow[128], uCol[128], pCol[128];
    __shared__ float slabA[128], slabB[128];
    uint32_t sb = smem_u32(smem);
    int tid = threadIdx.x, wid = tid >> 5, lane = tid & 31;

    // triangular tile index
    int t  = blockIdx.x;
    int bi = (int)((sqrtf(8.f * (float)t + 1.f) - 1.f) * 0.5f);
    while ((bi + 1) * (bi + 2) / 2 <= t) bi++;
    while (bi * (bi + 1) / 2 > t) bi--;
    int bj = t - bi * (bi + 1) / 2;
    int i0 = bi * 128, j0 = bj * 128;
    bool diag = (bi == bj);

    if (tid < 128) {
        uRow[tid] = 0.f; pRow[tid] = 0.f; uCol[tid] = 0.f; pCol[tid] = 0.f;
        slabA[tid] = labels[(i0 + tid) & (BSZ - 1)];
        slabB[tid] = labels[(j0 + tid) & (BSZ - 1)];
    }

    int lr = tid >> 2, lch = tid & 3;      // cp.async: 4x16B per 64B row, 64 rows/pass
    auto issue = [&](int c) {
        uint32_t stg = sb + (uint32_t)(c & 1) * STG;
        int gco = c * KC + lch * 8;
#pragma unroll
        for (int rr = 0; rr < 2; rr++) {
            int row = rr * 64 + lr;
            uint32_t d = stg + (uint32_t)(row * LDB + lch * 16);
            cpa16(d,           &g_Fhi[(size_t)(i0 + row) * DIM + gco]);
            cpa16(d + OPB,     &g_Flo[(size_t)(i0 + row) * DIM + gco]);
            cpa16(d + 2 * OPB, &g_Fhi[(size_t)(j0 + row) * DIM + gco]);
            cpa16(d + 3 * OPB, &g_Flo[(size_t)(j0 + row) * DIM + gco]);
        }
        CP_COMMIT();
    };

    int wr = wid & 1, wc = wid >> 1;       // warp tile = 64 rows x 32 cols
    int arow = (lane & 7) + ((lane >> 3) & 1) * 8;
    int acol = ((lane >> 4) & 1) * 8;
    int brow = (lane & 7) + ((lane >> 4) & 1) * 8;
    int bcol = ((lane >> 3) & 1) * 8;

    float acc[4][4][4];
#pragma unroll
    for (int mt = 0; mt < 4; mt++)
#pragma unroll
        for (int nt = 0; nt < 4; nt++)
#pragma unroll
            for (int e = 0; e < 4; e++) acc[mt][nt][e] = 0.f;

    issue(0); issue(1);
    for (int c = 0; c < NCHUNK; c++) {
        if (c == NCHUNK - 1) { CP_WAIT0(); } else { CP_WAIT1(); }
        __syncthreads();
        uint32_t stg = sb + (uint32_t)(c & 1) * STG;
#pragma unroll
        for (int ks = 0; ks < 2; ks++) {
            int k0 = ks * 16;
            uint32_t ah[4][4], al[4][4], bh[2][4], bl[2][4];
#pragma unroll
            for (int mt = 0; mt < 4; mt++) {
                int row = wr * 64 + mt * 16 + arow;
                uint32_t ad = stg + (uint32_t)(row * LDB + (k0 + acol) * 2);
                ldsm4(ah[mt], ad);
                ldsm4(al[mt], ad + OPB);
            }
#pragma unroll
            for (int pr = 0; pr < 2; pr++) {
                int row = wc * 32 + pr * 16 + brow;
                uint32_t bd = stg + (uint32_t)(2 * OPB + row * LDB + (k0 + bcol) * 2);
                ldsm4(bh[pr], bd);
                ldsm4(bl[pr], bd + OPB);
            }
#pragma unroll
            for (int sp = 0; sp < 3; sp++) {
#pragma unroll
                for (int mt = 0; mt < 4; mt++) {
#pragma unroll
                    for (int nt = 0; nt < 4; nt++) {
                        int pr = nt >> 1, h2 = (nt & 1) * 2;
                        uint32_t a0, a1, a2, a3, b0, b1;
                        if (sp == 2) { a0 = al[mt][0]; a1 = al[mt][1]; a2 = al[mt][2]; a3 = al[mt][3]; }
                        else         { a0 = ah[mt][0]; a1 = ah[mt][1]; a2 = ah[mt][2]; a3 = ah[mt][3]; }
                        if (sp == 1) { b0 = bl[pr][h2]; b1 = bl[pr][h2 + 1]; }
                        else         { b0 = bh[pr][h2]; b1 = bh[pr][h2 + 1]; }
                        mma_bf16(acc[mt][nt], a0, a1, a2, a3, b0, b1);
                    }
                }
            }
        }
        __syncthreads();
        if (c + 2 < NCHUNK) issue(c + 2);
    }

    // ---- fused epilogue ----
    const float invT = 1.0f / TEMP;
    float uR[8], pR[8], uC[8], pC[8];
#pragma unroll
    for (int e = 0; e < 8; e++) { uR[e] = 0.f; pR[e] = 0.f; uC[e] = 0.f; pC[e] = 0.f; }
    int rq = lane >> 2, cq = 2 * (lane & 3);
#pragma unroll
    for (int mt = 0; mt < 4; mt++) {
#pragma unroll
        for (int h = 0; h < 2; h++) {
            int r  = wr * 64 + mt * 16 + rq + h * 8;
            int iB = (i0 + r) & (BSZ - 1);
            float li = slabA[r];
            const unsigned short* dtrow = g_dt  + (size_t)iB * BSZ;
            const unsigned short* dTrow = g_dtT + (size_t)iB * BSZ;
            int ridx = mt * 2 + h;
#pragma unroll
            for (int nt = 0; nt < 4; nt++) {
                int c2  = wc * 32 + nt * 8 + cq;
                int jB2 = (j0 + c2) & (BSZ - 1);
                uint32_t dp  = *(const uint32_t*)(dtrow + jB2);
                uint32_t dTp = *(const uint32_t*)(dTrow + jB2);
#pragma unroll
                for (int e = 0; e < 2; e++) {
                    int cc = c2 + e;
                    float a = acc[mt][nt][h * 2 + e];
                    float x = (a - 1.0f) * invT;
                    float lj = slabB[cc];
                    float dd = li - lj;
                    float m  = __expf(-0.5f * dd * dd) * RSQRT2PI;
                    float ex = __expf(x);
                    float dv  = (float)((e ? (dp >> 16)  : dp)  & 0xFFFF);
                    float dTv = (float)((e ? (dTp >> 16) : dTp) & 0xFFFF);
                    bool skip = diag && (r == cc);
                    if (!skip) {
                        uR[ridx] += ex * dv;
                        pR[ridx]  = fmaf(m, x, pR[ridx]);
                        if (!diag) {
                            int cidx = nt * 2 + e;
                            uC[cidx] += ex * dTv;
                            pC[cidx]  = fmaf(m, x, pC[cidx]);
                        }
                    }
                }
            }
        }
    }
#pragma unroll
    for (int mt = 0; mt < 4; mt++)
#pragma unroll
        for (int h = 0; h < 2; h++) {
            int r = wr * 64 + mt * 16 + rq + h * 8;
            atomicAdd(&uRow[r], uR[mt * 2 + h]);
            atomicAdd(&pRow[r], pR[mt * 2 + h]);
        }
    if (!diag) {
#pragma unroll
        for (int nt = 0; nt < 4; nt++)
#pragma unroll
            for (int e = 0; e < 2; e++) {
                int cc = wc * 32 + nt * 8 + cq + e;
                atomicAdd(&uCol[cc], uC[nt * 2 + e]);
                atomicAdd(&pCol[cc], pC[nt * 2 + e]);
            }
    }
    __syncthreads();
    if (tid < 128) {
        atomicAdd(&g_u[i0 + tid], uRow[tid]);
        atomicAdd(&g_p[i0 + tid], pRow[tid]);
        if (!diag) {
            atomicAdd(&g_u[j0 + tid], uCol[tid]);
            atomicAdd(&g_p[j0 + tid], pCol[tid]);
        }
    }
}

// ---------------- K4: final reduction -----------------------------------------
__global__ void k_final(float* __restrict__ out) {
    __shared__ float red[512];
    int tid = threadIdx.x;
    float sum = 0.f;
    for (int i = tid; i < NTOT; i += 512) {
        float lp = g_p[i] / g_S[i & (BSZ - 1)] - logf(g_u[i]);
        sum += lp;
    }
    red[tid] = sum; __syncthreads();
    for (int st = 256; st > 0; st >>= 1) { if (tid < st) red[tid] += red[tid + st]; __syncthreads(); }
    if (tid == 0) out[0] = -red[0] / (float)NTOT;
}

// ---------------- entry --------------------------------------------------------
extern "C" void kernel_launch(void* const* d_in, const int* in_sizes, int n_in,
                              void* d_out, int out_size) {
    (void)in_sizes; (void)n_in; (void)out_size;
    const float* feats  = (const float*)d_in[0];
    const float* labels = (const float*)d_in[1];
    float* out = (float*)d_out;

    cudaFuncSetAttribute(k_main, cudaFuncAttributeMaxDynamicSharedMemorySize, DSMEM);

    k_prep  <<<1024, 256>>>(feats);
    k_sort  <<<1, 1024>>>(labels);
    k_tab   <<<2048, 256>>>(labels);
    k_transp<<<1024, 256>>>();
    k_main  <<<528, 256, DSMEM>>>(labels);
    k_final <<<1, 512>>>(out);
}